// round 1
// baseline (speedup 1.0000x reference)
#include <cuda_runtime.h>
#include <cuda_bf16.h>

// Problem constants
#define B_  16
#define S_  64
#define N_  196
#define H_  1024
#define F_  2048
#define E_  512

#define BS_ (B_ * S_)           // 1024
#define BN_ (B_ * N_)           // 3136
#define ATTN_ELEMS (BS_ * F_)   // 2097152  (attn_feats comes first in d_out)

// Scratch (allocation-free rule: __device__ globals)
__device__ float g_Wh[BS_ * E_];   // 2 MB
__device__ float g_Uv[BN_ * E_];   // 6.4 MB

// ---------------------------------------------------------------------------
// Batched fp32 SGEMM: C[M,N] = A[M,K] @ B[K,N], row-major.
// 64x64 tile, BK=16, 256 threads, 4x4 per thread. M,N must be multiples of 64
// (true for all three uses); K may be ragged (attn GEMM has K=196).
// ---------------------------------------------------------------------------
__global__ __launch_bounds__(256)
void sgemm64(const float* __restrict__ A, const float* __restrict__ B,
             float* __restrict__ C, int M, int N, int K,
             long long sA, long long sB, long long sC) {
    A += (long long)blockIdx.z * sA;
    B += (long long)blockIdx.z * sB;
    C += (long long)blockIdx.z * sC;

    __shared__ float As[16][64];   // As[k][m]
    __shared__ float Bs[16][64];   // Bs[k][n]

    const int tid  = threadIdx.x;
    const int row0 = blockIdx.y * 64;
    const int col0 = blockIdx.x * 64;
    const int tr = (tid >> 4) << 2;   // 0..60 step 4
    const int tc = (tid & 15) << 2;   // 0..60 step 4

    float acc[4][4] = {};

    for (int k0 = 0; k0 < K; k0 += 16) {
        // Load A tile (64 rows x 16 k) into As[k][m]
        #pragma unroll
        for (int i = 0; i < 4; i++) {
            int idx = tid + i * 256;          // 0..1023
            int r = idx >> 4;                 // 0..63
            int c = idx & 15;                 // 0..15
            int kk = k0 + c;
            As[c][r] = (kk < K) ? A[(long long)(row0 + r) * K + kk] : 0.f;
        }
        // Load B tile (16 k x 64 cols)
        #pragma unroll
        for (int i = 0; i < 4; i++) {
            int idx = tid + i * 256;
            int r = idx >> 6;                 // 0..15
            int c = idx & 63;                 // 0..63
            int kk = k0 + r;
            Bs[r][c] = (kk < K) ? B[(long long)kk * N + col0 + c] : 0.f;
        }
        __syncthreads();

        #pragma unroll
        for (int kk = 0; kk < 16; kk++) {
            float4 a4 = *reinterpret_cast<const float4*>(&As[kk][tr]);
            float4 b4 = *reinterpret_cast<const float4*>(&Bs[kk][tc]);
            float av[4] = {a4.x, a4.y, a4.z, a4.w};
            float bv[4] = {b4.x, b4.y, b4.z, b4.w};
            #pragma unroll
            for (int i = 0; i < 4; i++)
                #pragma unroll
                for (int j = 0; j < 4; j++)
                    acc[i][j] = fmaf(av[i], bv[j], acc[i][j]);
        }
        __syncthreads();
    }

    #pragma unroll
    for (int i = 0; i < 4; i++) {
        float4 out = make_float4(acc[i][0], acc[i][1], acc[i][2], acc[i][3]);
        *reinterpret_cast<float4*>(&C[(long long)(row0 + tr + i) * N + col0 + tc]) = out;
    }
}

// ---------------------------------------------------------------------------
// Fused scores + mask + softmax.
// One block per (b,s). 8 warps stride over n; each warp computes
//   score[n] = sum_e w[e] * tanh(Wh[b,s,e] + Uv[b,n,e] + bias[e])
// then block-wide softmax over the 196 scores -> weights output.
// ---------------------------------------------------------------------------
__global__ __launch_bounds__(256)
void scores_softmax_kernel(const float* __restrict__ Wh,
                           const float* __restrict__ Uv,
                           const float* __restrict__ bias,
                           const float* __restrict__ w,
                           const int* __restrict__ mask,
                           float* __restrict__ weights) {
    const int bs   = blockIdx.x;      // 0..1023
    const int b    = bs >> 6;
    const int tid  = threadIdx.x;
    const int warp = tid >> 5;
    const int lane = tid & 31;

    __shared__ float s_q[E_];
    __shared__ float s_w[E_];
    __shared__ float s_sc[N_];
    __shared__ float s_red[256];

    for (int e = tid; e < E_; e += 256) {
        s_q[e] = Wh[(long long)bs * E_ + e] + bias[e];
        s_w[e] = w[e];
    }
    __syncthreads();

    for (int n = warp; n < N_; n += 8) {
        const float* uv = Uv + (long long)(b * N_ + n) * E_;
        float sum = 0.f;
        #pragma unroll 4
        for (int e = lane; e < E_; e += 32) {
            float t;
            asm("tanh.approx.f32 %0, %1;" : "=f"(t) : "f"(s_q[e] + uv[e]));
            sum = fmaf(s_w[e], t, sum);
        }
        #pragma unroll
        for (int off = 16; off; off >>= 1)
            sum += __shfl_xor_sync(0xFFFFFFFFu, sum, off);
        if (lane == 0)
            s_sc[n] = (mask[b * N_ + n] == 0) ? -1e9f : sum;
    }
    __syncthreads();

    // Block softmax over 196 entries
    float v = (tid < N_) ? s_sc[tid] : -3.4e38f;
    s_red[tid] = v;
    __syncthreads();
    #pragma unroll
    for (int s = 128; s; s >>= 1) {
        if (tid < s) s_red[tid] = fmaxf(s_red[tid], s_red[tid + s]);
        __syncthreads();
    }
    float mx = s_red[0];
    __syncthreads();

    float ev = (tid < N_) ? __expf(v - mx) : 0.f;
    s_red[tid] = ev;
    __syncthreads();
    #pragma unroll
    for (int s = 128; s; s >>= 1) {
        if (tid < s) s_red[tid] += s_red[tid + s];
        __syncthreads();
    }
    float inv = 1.f / s_red[0];

    if (tid < N_)
        weights[(long long)bs * N_ + tid] = ev * inv;
}

// ---------------------------------------------------------------------------
// Launch
// ---------------------------------------------------------------------------
extern "C" void kernel_launch(void* const* d_in, const int* in_sizes, int n_in,
                              void* d_out, int out_size) {
    const float* hidden = (const float*)d_in[0];   // [16,64,1024]
    const float* feats  = (const float*)d_in[1];   // [16,196,2048]
    const int*   amask  = (const int*)  d_in[2];   // [16,196]
    const float* w_h    = (const float*)d_in[3];   // [1024,512]
    const float* w_u    = (const float*)d_in[4];   // [2048,512]
    const float* bias   = (const float*)d_in[5];   // [512]
    const float* w      = (const float*)d_in[6];   // [512]

    float* out_attn = (float*)d_out;               // [1024, 2048]
    float* out_wts  = (float*)d_out + ATTN_ELEMS;  // [1024, 196]

    float* Wh; cudaGetSymbolAddress((void**)&Wh, g_Wh);
    float* Uv; cudaGetSymbolAddress((void**)&Uv, g_Uv);

    // 1) Wh = hidden @ w_h : [1024,1024] @ [1024,512]
    {
        dim3 grid(E_ / 64, BS_ / 64, 1);
        sgemm64<<<grid, 256>>>(hidden, w_h, Wh, BS_, E_, H_, 0, 0, 0);
    }
    // 2) Uv = feats @ w_u : [3136,2048] @ [2048,512]
    {
        dim3 grid(E_ / 64, BN_ / 64, 1);
        sgemm64<<<grid, 256>>>(feats, w_u, Uv, BN_, E_, F_, 0, 0, 0);
    }
    // 3) fused scores + mask + softmax -> weights
    scores_softmax_kernel<<<BS_, 256>>>(Wh, Uv, bias, w, amask, out_wts);

    // 4) attn_feats[b] = weights[b] @ feats[b] : [64,196] @ [196,2048], batched over b
    {
        dim3 grid(F_ / 64, S_ / 64, B_);
        sgemm64<<<grid, 256>>>(out_wts, feats, out_attn, S_, F_, N_,
                               (long long)S_ * N_,
                               (long long)N_ * F_,
                               (long long)S_ * F_);
    }
}

// round 2
// speedup vs baseline: 2.5017x; 2.5017x over previous
#include <cuda_runtime.h>
#include <cuda_bf16.h>
#include <cstdint>

// Problem constants
#define B_  16
#define S_  64
#define N_  196
#define H_  1024
#define F_  2048
#define E_  512

#define BS_ (B_ * S_)           // 1024
#define BN_ (B_ * N_)           // 3136
#define ATTN_ELEMS (BS_ * F_)   // attn_feats first in d_out

// Scratch (allocation-free rule: __device__ globals)
__device__ float g_Wh[BS_ * E_];   // 2 MB
__device__ float g_Uv[BN_ * E_];   // 6.4 MB

// ---------------------------------------------------------------------------
// TF32 tensor-core GEMM: C[M,N] = A[M,K] @ B[K,N], row-major, fp32 in/out.
// BM=64, BN=128, BK=16, 256 threads (8 warps as 2x4), warp tile 32x32,
// mma.sync m16n8k8 tf32, cp.async double-buffered smem.
// Requires M%64==0, N%128==0, K%4==0 (ragged K zero-filled).
// ---------------------------------------------------------------------------
#define BM 64
#define BN 128
#define BK 16
#define PA 20    // A smem row stride (floats): banks (20r+c)%32 all distinct
#define PB 136   // B smem row stride (floats): banks (8k+n)%32 all distinct

__device__ __forceinline__ uint32_t f2tf32(float f) {
    uint32_t u;
    asm("cvt.rna.tf32.f32 %0, %1;" : "=r"(u) : "f"(f));
    return u;
}

__device__ __forceinline__ void mma_tf32(float* c, const uint32_t* a, const uint32_t* b) {
    asm volatile(
        "mma.sync.aligned.m16n8k8.row.col.f32.tf32.tf32.f32 "
        "{%0,%1,%2,%3}, {%4,%5,%6,%7}, {%8,%9}, {%0,%1,%2,%3};"
        : "+f"(c[0]), "+f"(c[1]), "+f"(c[2]), "+f"(c[3])
        : "r"(a[0]), "r"(a[1]), "r"(a[2]), "r"(a[3]), "r"(b[0]), "r"(b[1]));
}

__device__ __forceinline__ void cp_async16(uint32_t smem, const void* gmem, bool pred) {
    int sz = pred ? 16 : 0;
    asm volatile("cp.async.cg.shared.global [%0], [%1], 16, %2;"
                 :: "r"(smem), "l"(gmem), "r"(sz));
}

__global__ __launch_bounds__(256)
void gemm_tf32(const float* __restrict__ A, const float* __restrict__ B,
               float* __restrict__ C, int M, int N, int K,
               long long sA, long long sB, long long sC) {
    A += (long long)blockIdx.z * sA;
    B += (long long)blockIdx.z * sB;
    C += (long long)blockIdx.z * sC;

    __shared__ float As[2][BM][PA];
    __shared__ float Bs[2][BK][PB];

    const int tid    = threadIdx.x;
    const int wid    = tid >> 5;
    const int lane   = tid & 31;
    const int g      = lane >> 2;    // group id 0..7
    const int t      = lane & 3;     // thread-in-group 0..3
    const int warp_m = wid >> 2;     // 0..1
    const int warp_n = wid & 3;      // 0..3
    const int row0   = blockIdx.y * BM;
    const int col0   = blockIdx.x * BN;

    // Global->smem load assignments
    const int a_row = tid >> 2;           // 0..63
    const int a_col = (tid & 3) << 2;     // 0,4,8,12
    const int b_row0 = tid >> 5;          // 0..7  (two loads: +0, +8)
    const int b_col  = (tid & 31) << 2;   // 0..124

    const int nK = (K + BK - 1) / BK;

    float acc[2][4][4] = {};

    auto load_stage = [&](int stage, int k0) {
        // A tile: 64x16, one float4 per thread
        {
            int kk = k0 + a_col;
            uint32_t s = (uint32_t)__cvta_generic_to_shared(&As[stage][a_row][a_col]);
            cp_async16(s, A + (long long)(row0 + a_row) * K + kk, kk < K);
        }
        // B tile: 16x128, two float4 per thread
        #pragma unroll
        for (int i = 0; i < 2; i++) {
            int br = b_row0 + i * 8;
            int kk = k0 + br;
            uint32_t s = (uint32_t)__cvta_generic_to_shared(&Bs[stage][br][b_col]);
            cp_async16(s, B + (long long)kk * N + col0 + b_col, kk < K);
        }
    };

    load_stage(0, 0);
    asm volatile("cp.async.commit_group;");

    for (int it = 0; it < nK; it++) {
        int cur = it & 1;
        if (it + 1 < nK) load_stage(cur ^ 1, (it + 1) * BK);
        asm volatile("cp.async.commit_group;");
        asm volatile("cp.async.wait_group 1;");
        __syncthreads();

        #pragma unroll
        for (int k8 = 0; k8 < 2; k8++) {
            const int kb = k8 * 8;
            uint32_t af[2][4], bf[4][2];
            #pragma unroll
            for (int i = 0; i < 2; i++) {
                int rb = warp_m * 32 + i * 16;
                af[i][0] = f2tf32(As[cur][rb + g    ][kb + t    ]);
                af[i][1] = f2tf32(As[cur][rb + g + 8][kb + t    ]);
                af[i][2] = f2tf32(As[cur][rb + g    ][kb + t + 4]);
                af[i][3] = f2tf32(As[cur][rb + g + 8][kb + t + 4]);
            }
            #pragma unroll
            for (int j = 0; j < 4; j++) {
                int cb = warp_n * 32 + j * 8;
                bf[j][0] = f2tf32(Bs[cur][kb + t    ][cb + g]);
                bf[j][1] = f2tf32(Bs[cur][kb + t + 4][cb + g]);
            }
            #pragma unroll
            for (int i = 0; i < 2; i++)
                #pragma unroll
                for (int j = 0; j < 4; j++)
                    mma_tf32(acc[i][j], af[i], bf[j]);
        }
        __syncthreads();
    }

    // Epilogue: c0,c1 at (row g, cols 2t,2t+1); c2,c3 at row g+8
    #pragma unroll
    for (int i = 0; i < 2; i++) {
        #pragma unroll
        for (int j = 0; j < 4; j++) {
            int r = row0 + warp_m * 32 + i * 16 + g;
            int c = col0 + warp_n * 32 + j * 8 + 2 * t;
            float2 v0 = make_float2(acc[i][j][0], acc[i][j][1]);
            float2 v1 = make_float2(acc[i][j][2], acc[i][j][3]);
            *reinterpret_cast<float2*>(&C[(long long)r * N + c]) = v0;
            *reinterpret_cast<float2*>(&C[(long long)(r + 8) * N + c]) = v1;
        }
    }
}

// ---------------------------------------------------------------------------
// Fused scores + mask + softmax (unchanged from round 1).
// ---------------------------------------------------------------------------
__global__ __launch_bounds__(256)
void scores_softmax_kernel(const float* __restrict__ Wh,
                           const float* __restrict__ Uv,
                           const float* __restrict__ bias,
                           const float* __restrict__ w,
                           const int* __restrict__ mask,
                           float* __restrict__ weights) {
    const int bs   = blockIdx.x;
    const int b    = bs >> 6;
    const int tid  = threadIdx.x;
    const int warp = tid >> 5;
    const int lane = tid & 31;

    __shared__ float s_q[E_];
    __shared__ float s_w[E_];
    __shared__ float s_sc[N_];
    __shared__ float s_red[256];

    for (int e = tid; e < E_; e += 256) {
        s_q[e] = Wh[(long long)bs * E_ + e] + bias[e];
        s_w[e] = w[e];
    }
    __syncthreads();

    for (int n = warp; n < N_; n += 8) {
        const float* uv = Uv + (long long)(b * N_ + n) * E_;
        float sum = 0.f;
        #pragma unroll 4
        for (int e = lane; e < E_; e += 32) {
            float tval;
            asm("tanh.approx.f32 %0, %1;" : "=f"(tval) : "f"(s_q[e] + uv[e]));
            sum = fmaf(s_w[e], tval, sum);
        }
        #pragma unroll
        for (int off = 16; off; off >>= 1)
            sum += __shfl_xor_sync(0xFFFFFFFFu, sum, off);
        if (lane == 0)
            s_sc[n] = (mask[b * N_ + n] == 0) ? -1e9f : sum;
    }
    __syncthreads();

    float v = (tid < N_) ? s_sc[tid] : -3.4e38f;
    s_red[tid] = v;
    __syncthreads();
    #pragma unroll
    for (int s = 128; s; s >>= 1) {
        if (tid < s) s_red[tid] = fmaxf(s_red[tid], s_red[tid + s]);
        __syncthreads();
    }
    float mx = s_red[0];
    __syncthreads();

    float ev = (tid < N_) ? __expf(v - mx) : 0.f;
    s_red[tid] = ev;
    __syncthreads();
    #pragma unroll
    for (int s = 128; s; s >>= 1) {
        if (tid < s) s_red[tid] += s_red[tid + s];
        __syncthreads();
    }
    float inv = 1.f / s_red[0];

    if (tid < N_)
        weights[(long long)bs * N_ + tid] = ev * inv;
}

// ---------------------------------------------------------------------------
// Launch
// ---------------------------------------------------------------------------
extern "C" void kernel_launch(void* const* d_in, const int* in_sizes, int n_in,
                              void* d_out, int out_size) {
    const float* hidden = (const float*)d_in[0];   // [16,64,1024]
    const float* feats  = (const float*)d_in[1];   // [16,196,2048]
    const int*   amask  = (const int*)  d_in[2];   // [16,196]
    const float* w_h    = (const float*)d_in[3];   // [1024,512]
    const float* w_u    = (const float*)d_in[4];   // [2048,512]
    const float* bias   = (const float*)d_in[5];   // [512]
    const float* w      = (const float*)d_in[6];   // [512]

    float* out_attn = (float*)d_out;               // [1024, 2048]
    float* out_wts  = (float*)d_out + ATTN_ELEMS;  // [1024, 196]

    float* Wh; cudaGetSymbolAddress((void**)&Wh, g_Wh);
    float* Uv; cudaGetSymbolAddress((void**)&Uv, g_Uv);

    // 1) Wh = hidden @ w_h : [1024,1024] @ [1024,512]
    {
        dim3 grid(E_ / BN, BS_ / BM, 1);
        gemm_tf32<<<grid, 256>>>(hidden, w_h, Wh, BS_, E_, H_, 0, 0, 0);
    }
    // 2) Uv = feats @ w_u : [3136,2048] @ [2048,512]
    {
        dim3 grid(E_ / BN, BN_ / BM, 1);
        gemm_tf32<<<grid, 256>>>(feats, w_u, Uv, BN_, E_, F_, 0, 0, 0);
    }
    // 3) fused scores + mask + softmax -> weights
    scores_softmax_kernel<<<BS_, 256>>>(Wh, Uv, bias, w, amask, out_wts);

    // 4) attn_feats[b] = weights[b] @ feats[b] : [64,196]@[196,2048] batched
    {
        dim3 grid(F_ / BN, S_ / BM, B_);
        gemm_tf32<<<grid, 256>>>(out_wts, feats, out_attn, S_, F_, N_,
                                 (long long)S_ * N_,
                                 (long long)N_ * F_,
                                 (long long)S_ * F_);
    }
}